// round 9
// baseline (speedup 1.0000x reference)
#include <cuda_runtime.h>
#include <cuda_fp16.h>
#include <cstdint>

#define NN 512
#define HH 8
#define RDC 4096
#define MRN 65536
#define DPL 2097152   // one dots plane = 8*512*512
#define STG_H 5120    // halves per smem stage (128*40)
#define NSTG 5
#define SMEM_BYTES 102400   // 5 stages * (10240 A + 10240 B)

__device__ __align__(16) __half g_xh  [MRN * 128];
__device__ __align__(16) __half g_wt  [896 * 128];
__device__ __align__(16) __half g_woutt[128 * 256];
__device__ __align__(16) __half g_qh  [HH * NN * RDC];
__device__ __align__(16) __half g_kh  [HH * NN * RDC];
__device__ __align__(16) __half g_vh  [HH * NN * RDC];
__device__ __align__(16) __half g_ph  [HH * NN * NN];
__device__ __align__(16) __half g_o2  [MRN * 256];
__device__ __align__(16) float  g_dots[4 * DPL];
__device__ __align__(16) float  g_pbh [HH * NN * NN];
__device__ __align__(16) float  g_ksw [MRN * 128];
__device__ __align__(16) float  g_qsw [NN * 128];
__device__ __align__(16) float  g_wrow[NN * HH * 128];

__device__ __forceinline__ uint32_t smem_u32(const void* p) {
    uint32_t a;
    asm("{ .reg .u64 t; cvta.to.shared.u64 t, %1; cvt.u32.u64 %0, t; }" : "=r"(a) : "l"(p));
    return a;
}
__device__ __forceinline__ void ldm4(uint32_t* r, uint32_t addr) {
    asm volatile("ldmatrix.sync.aligned.m8n8.x4.shared.b16 {%0,%1,%2,%3}, [%4];"
                 : "=r"(r[0]), "=r"(r[1]), "=r"(r[2]), "=r"(r[3]) : "r"(addr));
}
__device__ __forceinline__ void ldm4t(uint32_t* r, uint32_t addr) {
    asm volatile("ldmatrix.sync.aligned.m8n8.x4.trans.shared.b16 {%0,%1,%2,%3}, [%4];"
                 : "=r"(r[0]), "=r"(r[1]), "=r"(r[2]), "=r"(r[3]) : "r"(addr));
}
__device__ __forceinline__ void mma16(float* c, const uint32_t* a, const uint32_t* b) {
    asm volatile("mma.sync.aligned.m16n8k16.row.col.f32.f16.f16.f32 "
        "{%0,%1,%2,%3},{%4,%5,%6,%7},{%8,%9},{%0,%1,%2,%3};"
        : "+f"(c[0]), "+f"(c[1]), "+f"(c[2]), "+f"(c[3])
        : "r"(a[0]), "r"(a[1]), "r"(a[2]), "r"(a[3]), "r"(b[0]), "r"(b[1]));
}
#define CPA16(dst, src) \
    asm volatile("cp.async.cg.shared.global [%0], [%1], 16;" :: "r"(dst), "l"(src) : "memory")

// ============================================================================
// fp16 GEMM: block 128x128, 8 warps (64x32), ktile 32, 5-stage deep pipeline.
// Per iter: wait(group kt) -> barrier -> issue(kt+4) -> compute(kt).
// MODE: 0=qkv, 1=dots(split-K=4), 2=O trans-B, 3=out, 4=ksw
// ============================================================================
template<int MODE, int KT>
__global__ __launch_bounds__(256) void g16(const float* __restrict__ auxA,
                                           float* __restrict__ outp) {
    extern __shared__ __half sh[];
    __half* AsB = sh;
    __half* BsB = sh + NSTG * STG_H;
    const int t = threadIdx.x, lane = t & 31, warp = t >> 5;
    const int bx = blockIdx.x, by = blockIdx.y;
    const int h = (MODE == 1) ? (blockIdx.z & 7) : blockIdx.z;
    const int split = (MODE == 1) ? (blockIdx.z >> 3) : 0;

    const __half *A, *B; int lda, ldb;
    if (MODE == 0)      { A = g_xh + (size_t)by * 128 * 128; lda = 128;
                          B = g_wt + (size_t)bx * 128 * 128; ldb = 128; }
    else if (MODE == 4) { A = g_xh + (size_t)by * 128 * 128; lda = 128;
                          B = g_wt + (size_t)768 * 128;      ldb = 128; }
    else if (MODE == 1) { A = g_qh + ((size_t)h * 512 + by * 128) * 4096 + split * 1024; lda = 4096;
                          B = g_kh + ((size_t)h * 512 + bx * 128) * 4096 + split * 1024; ldb = 4096; }
    else if (MODE == 2) { A = g_ph + ((size_t)h * 512 + by * 128) * 512; lda = 512;
                          B = g_vh + (size_t)h * 512 * 4096 + bx * 128;  ldb = 4096; }
    else                { A = g_o2 + (size_t)by * 128 * 256; lda = 256;
                          B = g_woutt;                       ldb = 256; }

    auto cpst = [&](int st, int k0) {
        uint32_t da = smem_u32(AsB + st * STG_H), db = smem_u32(BsB + st * STG_H);
#pragma unroll
        for (int c = t; c < 512; c += 256) {
            int row = c >> 2, col = c & 3;
            CPA16(da + row * 80 + col * 16, A + (size_t)row * lda + k0 + col * 8);
        }
        if (MODE == 2) {
#pragma unroll
            for (int c = t; c < 512; c += 256) {
                int row = c >> 4, col = c & 15;
                CPA16(db + row * 272 + col * 16, B + (size_t)(k0 + row) * ldb + col * 8);
            }
        } else {
#pragma unroll
            for (int c = t; c < 512; c += 256) {
                int row = c >> 2, col = c & 3;
                CPA16(db + row * 80 + col * 16, B + (size_t)row * ldb + k0 + col * 8);
            }
        }
        asm volatile("cp.async.commit_group;" ::: "memory");
    };

    float acc[4][4][4] = {};
    const int wm0 = (warp >> 2) * 64, wn0 = (warp & 3) * 32;
    const int q = lane >> 3;

    // prologue: 4 chunks in flight
#pragma unroll
    for (int c = 0; c < 4 && c < KT; c++) cpst(c, c * 32);

    int st = 0;
    for (int kt = 0; kt < KT; kt++) {
        // wait for group kt: allowed pending = min(3, KT-kt-1)
        if (kt < KT - 3)       asm volatile("cp.async.wait_group 3;" ::: "memory");
        else if (kt == KT - 3) asm volatile("cp.async.wait_group 2;" ::: "memory");
        else if (kt == KT - 2) asm volatile("cp.async.wait_group 1;" ::: "memory");
        else                   asm volatile("cp.async.wait_group 0;" ::: "memory");
        __syncthreads();                       // all threads' copies for stage st visible

        if (kt + 4 < KT) {
            int ns = st + 4; if (ns >= NSTG) ns -= NSTG;   // == (kt-1)%5, consumers past barrier
            cpst(ns, (kt + 4) * 32);
        }

        uint32_t ab = smem_u32(AsB + st * STG_H), bb = smem_u32(BsB + st * STG_H);
#pragma unroll
        for (int kk = 0; kk < 32; kk += 16) {
            uint32_t af[4][4], bf[2][4];
#pragma unroll
            for (int mt = 0; mt < 4; mt++)
                ldm4(af[mt], ab + (wm0 + mt * 16 + (lane & 15)) * 80 + (kk + (lane >> 4) * 8) * 2);
#pragma unroll
            for (int np = 0; np < 2; np++) {
                if (MODE == 2)
                    ldm4t(bf[np], bb + (kk + (q & 1) * 8 + (lane & 7)) * 272
                                     + (wn0 + np * 16 + (q >> 1) * 8) * 2);
                else
                    ldm4(bf[np], bb + (wn0 + np * 16 + (q >> 1) * 8 + (lane & 7)) * 80
                                    + (kk + (q & 1) * 8) * 2);
            }
#pragma unroll
            for (int mt = 0; mt < 4; mt++)
#pragma unroll
                for (int nt = 0; nt < 4; nt++)
                    mma16(acc[mt][nt], af[mt], &bf[nt >> 1][(nt & 1) * 2]);
        }
        st++; if (st == NSTG) st = 0;
    }

#pragma unroll
    for (int mt = 0; mt < 4; mt++)
#pragma unroll
        for (int nt = 0; nt < 4; nt++)
#pragma unroll
            for (int hf = 0; hf < 2; hf++) {
                int mrow = wm0 + mt * 16 + (lane >> 2) + hf * 8;
                int ncol = wn0 + nt * 8 + (lane & 3) * 2;
                float v0 = acc[mt][nt][hf * 2], v1 = acc[mt][nt][hf * 2 + 1];
                if (MODE == 0) {
                    int m = by * 128 + mrow, c = bx * 128 + ncol;
                    int r = m >> 9, n = m & 511;
                    if (c < 256) {
                        int hh = c >> 5, d = c & 31;
                        float w = g_wrow[(n * 8 + hh) * 128 + r];
                        *reinterpret_cast<__half2*>(
                            &g_qh[((size_t)(hh * 512 + n)) * 4096 + r * 32 + d]) =
                            __floats2half2_rn(v0 * w, v1 * w);
                    } else if (c < 512) {
                        int cc = c - 256, hh = cc >> 5, d = cc & 31;
                        *reinterpret_cast<__half2*>(
                            &g_kh[((size_t)(hh * 512 + n)) * 4096 + r * 32 + d]) =
                            __floats2half2_rn(v0, v1);
                    } else {
                        int cc = c - 512, hh = cc >> 5, d = cc & 31;
                        *reinterpret_cast<__half2*>(
                            &g_vh[((size_t)(hh * 512 + n)) * 4096 + r * 32 + d]) =
                            __floats2half2_rn(v0, v1);
                    }
                } else if (MODE == 4) {
                    int m = by * 128 + mrow;
                    g_ksw[(size_t)m * 128 + ncol]     = v0 + auxA[ncol];
                    g_ksw[(size_t)m * 128 + ncol + 1] = v1 + auxA[ncol + 1];
                } else if (MODE == 1) {
                    int i = by * 128 + mrow, j = bx * 128 + ncol;
                    size_t off = (size_t)split * DPL + ((size_t)h * 512 + i) * 512 + j;
                    g_dots[off]     = v0;
                    g_dots[off + 1] = v1;
                } else if (MODE == 2) {
                    int i = by * 128 + mrow, tcol = bx * 128 + ncol;
                    int r = tcol >> 5, d = tcol & 31;
                    *reinterpret_cast<__half2*>(
                        &g_o2[((size_t)r * 512 + i) * 256 + h * 32 + d]) =
                        __floats2half2_rn(v0, v1);
                } else {
                    int m = by * 128 + mrow;
                    outp[(size_t)m * 128 + ncol]     = v0 + auxA[ncol];
                    outp[(size_t)m * 128 + ncol + 1] = v1 + auxA[ncol + 1];
                }
            }
}

// ============================================================================
__global__ void conv_x(const float* __restrict__ x) {
    size_t i = ((size_t)blockIdx.x * 256 + threadIdx.x) * 4;
    float4 v = *reinterpret_cast<const float4*>(x + i);
    __half2* d = reinterpret_cast<__half2*>(&g_xh[i]);
    d[0] = __floats2half2_rn(v.x, v.y);
    d[1] = __floats2half2_rn(v.z, v.w);
}

__global__ void conv_w(const float* __restrict__ Wq, const float* __restrict__ Wkv,
                       const float* __restrict__ Wk_sw, const float* __restrict__ Wout) {
    int g = blockIdx.x * 256 + threadIdx.x;
    if (g < 114688) {
        int row = g >> 7, k = g & 127;
        float v;
        if (row < 256)      v = Wq[k * 256 + row];
        else if (row < 768) v = Wkv[k * 512 + (row - 256)];
        else                v = Wk_sw[k * 128 + (row - 768)];
        g_wt[g] = __float2half_rn(v);
    } else {
        int g2 = g - 114688;
        int c = g2 >> 8, k = g2 & 255;
        g_woutt[g2] = __float2half_rn(Wout[k * 128 + c]);
    }
}

__global__ void qsw_kernel(const float* __restrict__ x, const float* __restrict__ Wq_sw,
                           const float* __restrict__ bq_sw) {
    int n = blockIdx.x, c = threadIdx.x;
    __shared__ float xr[128];
    xr[c] = x[(size_t)n * 128 + c];
    __syncthreads();
    float acc = bq_sw[c];
#pragma unroll 8
    for (int k = 0; k < 128; k++) acc += xr[k] * Wq_sw[k * 128 + c];
    g_qsw[n * 128 + c] = acc;
}

__global__ void sw_reduce_kernel() {
    int m = blockIdx.x, r = m >> 9, n = m & 511, c = threadIdx.x;
    float prod = g_ksw[(size_t)m * 128 + c] * g_qsw[n * 128 + c];
#pragma unroll
    for (int o = 8; o; o >>= 1) prod += __shfl_down_sync(0xffffffffu, prod, o, 16);
    if ((c & 15) == 0) g_wrow[(n * 8 + (c >> 4)) * 128 + r] = prod * 0.25f;
}

__global__ void wrow_softmax_kernel() {
    int row = blockIdx.x, t = threadIdx.x;
    float v = g_wrow[(size_t)row * 128 + t];
    __shared__ float sm[128];
    sm[t] = v; __syncthreads();
#pragma unroll
    for (int s = 64; s > 0; s >>= 1) { if (t < s) sm[t] = fmaxf(sm[t], sm[t + s]); __syncthreads(); }
    float mx = sm[0]; __syncthreads();
    float e = expf(v - mx);
    sm[t] = e; __syncthreads();
#pragma unroll
    for (int s = 64; s > 0; s >>= 1) { if (t < s) sm[t] += sm[t + s]; __syncthreads(); }
    g_wrow[(size_t)row * 128 + t] = e / sm[0];
}

__global__ void pbh_kernel(const float* __restrict__ pair_bias, const float* __restrict__ ln_g,
                           const float* __restrict__ ln_b, const float* __restrict__ Wpair) {
    int warp = threadIdx.x >> 5, lane = threadIdx.x & 31;
    int idx = blockIdx.x * 8 + warp;
    int i = idx >> 9, j = idx & 511;
    float4 v = *reinterpret_cast<const float4*>(&pair_bias[(size_t)idx * 128 + lane * 4]);
    float s  = v.x + v.y + v.z + v.w;
    float sq = v.x * v.x + v.y * v.y + v.z * v.z + v.w * v.w;
#pragma unroll
    for (int o = 16; o; o >>= 1) {
        s  += __shfl_xor_sync(0xffffffffu, s, o);
        sq += __shfl_xor_sync(0xffffffffu, sq, o);
    }
    float mean = s * (1.0f / 128.0f);
    float var  = sq * (1.0f / 128.0f) - mean * mean;
    float rstd = rsqrtf(var + 1e-5f);
    float vv[4] = {v.x, v.y, v.z, v.w};
    float ph[8] = {};
#pragma unroll
    for (int e = 0; e < 4; e++) {
        int p = lane * 4 + e;
        float nz = (vv[e] - mean) * rstd * ln_g[p] + ln_b[p];
#pragma unroll
        for (int hh = 0; hh < 8; hh++) ph[hh] += nz * Wpair[p * 8 + hh];
    }
#pragma unroll
    for (int hh = 0; hh < 8; hh++)
#pragma unroll
        for (int o = 16; o; o >>= 1) ph[hh] += __shfl_xor_sync(0xffffffffu, ph[hh], o);
    if (lane == 0)
#pragma unroll
        for (int hh = 0; hh < 8; hh++) g_pbh[(((size_t)hh << 9) + i) * NN + j] = ph[hh];
}

__global__ void attn_softmax_kernel() {
    size_t row = blockIdx.x;
    int t = threadIdx.x;
    size_t off0 = row * 512 + t, off1 = off0 + 256;
    const float scale = 0.17677669529663687f;
    float v0 = (g_dots[off0] + g_dots[off0 + DPL] + g_dots[off0 + 2 * DPL] + g_dots[off0 + 3 * DPL])
               * scale + g_pbh[off0];
    float v1 = (g_dots[off1] + g_dots[off1 + DPL] + g_dots[off1 + 2 * DPL] + g_dots[off1 + 3 * DPL])
               * scale + g_pbh[off1];
    __shared__ float sm[256];
    sm[t] = fmaxf(v0, v1); __syncthreads();
#pragma unroll
    for (int s = 128; s > 0; s >>= 1) { if (t < s) sm[t] = fmaxf(sm[t], sm[t + s]); __syncthreads(); }
    float mx = sm[0]; __syncthreads();
    float e0 = expf(v0 - mx), e1 = expf(v1 - mx);
    sm[t] = e0 + e1; __syncthreads();
#pragma unroll
    for (int s = 128; s > 0; s >>= 1) { if (t < s) sm[t] += sm[t + s]; __syncthreads(); }
    float inv = 1.0f / sm[0];
    g_ph[row * 512 + t]       = __float2half_rn(e0 * inv);
    g_ph[row * 512 + t + 256] = __float2half_rn(e1 * inv);
}

// ============================================================================
extern "C" void kernel_launch(void* const* d_in, const int* in_sizes, int n_in,
                              void* d_out, int out_size) {
    (void)in_sizes; (void)n_in; (void)out_size;
    const float* x         = (const float*)d_in[0];
    const float* pair_bias = (const float*)d_in[1];
    const float* Wq        = (const float*)d_in[2];
    const float* Wkv       = (const float*)d_in[3];
    const float* Wout      = (const float*)d_in[4];
    const float* b_out     = (const float*)d_in[5];
    const float* ln_g      = (const float*)d_in[6];
    const float* ln_b      = (const float*)d_in[7];
    const float* Wpair     = (const float*)d_in[8];
    const float* Wq_sw     = (const float*)d_in[9];
    const float* bq_sw     = (const float*)d_in[10];
    const float* Wk_sw     = (const float*)d_in[11];
    const float* bk_sw     = (const float*)d_in[12];
    float* out = (float*)d_out;

    static int attr_done = 0;
    if (!attr_done) {
        cudaFuncSetAttribute(g16<0, 4>,  cudaFuncAttributeMaxDynamicSharedMemorySize, SMEM_BYTES);
        cudaFuncSetAttribute(g16<1, 32>, cudaFuncAttributeMaxDynamicSharedMemorySize, SMEM_BYTES);
        cudaFuncSetAttribute(g16<2, 16>, cudaFuncAttributeMaxDynamicSharedMemorySize, SMEM_BYTES);
        cudaFuncSetAttribute(g16<3, 8>,  cudaFuncAttributeMaxDynamicSharedMemorySize, SMEM_BYTES);
        cudaFuncSetAttribute(g16<4, 4>,  cudaFuncAttributeMaxDynamicSharedMemorySize, SMEM_BYTES);
        attr_done = 1;
    }

    conv_x             <<<8192, 256>>>(x);
    conv_w             <<<576, 256>>>(Wq, Wkv, Wk_sw, Wout);
    qsw_kernel         <<<NN, 128>>>(x, Wq_sw, bq_sw);
    g16<4, 4>          <<<dim3(1, 512), 256, SMEM_BYTES>>>(bk_sw, nullptr);      // ksw
    sw_reduce_kernel   <<<MRN, 128>>>();
    wrow_softmax_kernel<<<NN * HH, 128>>>();
    g16<0, 4>          <<<dim3(6, 512), 256, SMEM_BYTES>>>(nullptr, nullptr);    // qkv
    pbh_kernel         <<<NN * NN / 8, 256>>>(pair_bias, ln_g, ln_b, Wpair);
    g16<1, 32>         <<<dim3(4, 4, 32), 256, SMEM_BYTES>>>(nullptr, nullptr);  // dots sK=4
    attn_softmax_kernel<<<HH * NN, 256>>>();
    g16<2, 16>         <<<dim3(32, 4, 8), 256, SMEM_BYTES>>>(nullptr, nullptr);  // O
    g16<3, 8>          <<<dim3(1, 512), 256, SMEM_BYTES>>>(b_out, out);          // out
}